// round 2
// baseline (speedup 1.0000x reference)
#include <cuda_runtime.h>
#include <cuda_bf16.h>
#include <cstdint>

// Problem constants (fixed shapes for this problem)
#define D      768
#define QTOT   512
#define NTOT   262144
#define KTOP   10

#define QT     32          // queries per block (kernel B)
#define CHUNK  4096        // lib rows per block (kernel B)
#define NCHUNK (NTOT / CHUNK)   // 64
#define STRIP  256         // lib rows per strip
#define BK     32          // k-chunk

// ---------------- scratch (no allocations allowed) ----------------
__device__ float g_xsq[NTOT];
__device__ float g_qsq[QTOT];
__device__ float g_pd[(size_t)QTOT * NCHUNK * KTOP];
__device__ int   g_pi[(size_t)QTOT * NCHUNK * KTOP];

// ---------------- kernel A: squared row norms ----------------
__global__ void sqnorm_kernel(const float* __restrict__ x, int rows, int which) {
    int w    = (blockIdx.x * blockDim.x + threadIdx.x) >> 5;
    int lane = threadIdx.x & 31;
    if (w >= rows) return;
    const float* r = x + (size_t)w * D;
    float s = 0.f;
#pragma unroll
    for (int t = 0; t < D / 32; t++) {
        float v = r[lane + t * 32];
        s = fmaf(v, v, s);
    }
#pragma unroll
    for (int o = 16; o; o >>= 1) s += __shfl_xor_sync(0xffffffffu, s, o);
    if (lane == 0) {
        if (which) g_qsq[w] = s; else g_xsq[w] = s;
    }
}

// ---------------- kernel B: tiled GEMM + per-chunk top-10 ----------------
__global__ __launch_bounds__(256)
void dist_topk_kernel(const float* __restrict__ query, const float* __restrict__ lib) {
    __shared__ float ls[STRIP * 33];     // lib strip, stride-33 pad (conflict-free)
    __shared__ float qs[QT * 33];        // query tile
    __shared__ float s_topd[QT * KTOP];
    __shared__ int   s_topi[QT * KTOP];

    const int tid   = threadIdx.x;
    const int lane  = tid & 31;
    const int warp  = tid >> 5;          // 8 warps; warp owns queries warp*4..+3
    const int q0    = blockIdx.y * QT;
    const int c0    = blockIdx.x * CHUNK;

    // init top-k
    for (int t = tid; t < QT * KTOP; t += 256) {
        s_topd[t] = __int_as_float(0x7f800000);   // +INF
        s_topi[t] = 0;
    }
    __syncthreads();

    // per-warp query sq-norms
    float qsq_r[4];
#pragma unroll
    for (int qq = 0; qq < 4; qq++) qsq_r[qq] = g_qsq[q0 + warp * 4 + qq];

    for (int s = 0; s < CHUNK / STRIP; s++) {
        const int strip0 = s * STRIP;
        float acc[4][8];
#pragma unroll
        for (int a = 0; a < 4; a++)
#pragma unroll
            for (int b = 0; b < 8; b++) acc[a][b] = 0.f;

        for (int kc = 0; kc < D; kc += BK) {
            __syncthreads();
            // load lib strip [STRIP x BK] -> ls, scalar STS to keep stride-33 layout
#pragma unroll
            for (int it = 0; it < 8; it++) {
                int f4  = tid + it * 256;          // 0..2047
                int row = f4 >> 3;
                int c4  = f4 & 7;
                float4 v = *(const float4*)(lib + (size_t)(c0 + strip0 + row) * D + kc + c4 * 4);
                float* dst = &ls[row * 33 + c4 * 4];
                dst[0] = v.x; dst[1] = v.y; dst[2] = v.z; dst[3] = v.w;
            }
            // load query tile [QT x BK]
            {
                int row = tid >> 3;
                int c4  = tid & 7;
                float4 v = *(const float4*)(query + (size_t)(q0 + row) * D + kc + c4 * 4);
                float* dst = &qs[row * 33 + c4 * 4];
                dst[0] = v.x; dst[1] = v.y; dst[2] = v.z; dst[3] = v.w;
            }
            __syncthreads();
            // accumulate
#pragma unroll
            for (int kk = 0; kk < BK; kk++) {
                float a0 = qs[(warp * 4 + 0) * 33 + kk];
                float a1 = qs[(warp * 4 + 1) * 33 + kk];
                float a2 = qs[(warp * 4 + 2) * 33 + kk];
                float a3 = qs[(warp * 4 + 3) * 33 + kk];
#pragma unroll
                for (int j = 0; j < 8; j++) {
                    float b = ls[(lane + j * 32) * 33 + kk];
                    acc[0][j] = fmaf(a0, b, acc[0][j]);
                    acc[1][j] = fmaf(a1, b, acc[1][j]);
                    acc[2][j] = fmaf(a2, b, acc[2][j]);
                    acc[3][j] = fmaf(a3, b, acc[3][j]);
                }
            }
        }

        // lib sq-norms for this strip
        float lx[8];
#pragma unroll
        for (int j = 0; j < 8; j++) lx[j] = g_xsq[c0 + strip0 + lane + j * 32];

        // top-k insertion: each warp exclusively owns its 4 queries' arrays
#pragma unroll
        for (int qq = 0; qq < 4; qq++) {
            int q = warp * 4 + qq;
            float* td = &s_topd[q * KTOP];
            int*   ti = &s_topi[q * KTOP];
#pragma unroll
            for (int j = 0; j < 8; j++) {
                float d = qsq_r[qq] - 2.f * acc[qq][j] + lx[j];
                __syncwarp();
                float worst = td[KTOP - 1];
                unsigned m = __ballot_sync(0xffffffffu, d < worst);
                while (m) {
                    int src = __ffs(m) - 1;
                    m &= m - 1;
                    float dd = __shfl_sync(0xffffffffu, d, src);
                    if (lane == 0) {
                        if (dd < td[KTOP - 1]) {
                            int ii = c0 + strip0 + src + j * 32;
                            int p = KTOP - 1;
                            while (p > 0 && td[p - 1] > dd) {
                                td[p] = td[p - 1]; ti[p] = ti[p - 1]; p--;
                            }
                            td[p] = dd; ti[p] = ii;
                        }
                    }
                    __syncwarp();
                }
            }
        }
    }

    __syncthreads();
    // write partials [q][chunk][k]
    for (int t = tid; t < QT * KTOP; t += 256) {
        int q = t / KTOP, j = t % KTOP;
        size_t off = ((size_t)(q0 + q) * NCHUNK + blockIdx.x) * KTOP + j;
        g_pd[off] = s_topd[t];
        g_pi[off] = s_topi[t];
    }
}

// ---------------- kernel C: merge partials -> global top-10 ----------------
__global__ void merge_kernel(float* __restrict__ out) {
    const int q   = blockIdx.x;
    const int tid = threadIdx.x;            // 128 threads
    const int total = NCHUNK * KTOP;        // 640

    __shared__ float cd[NCHUNK * KTOP];
    __shared__ int   ci[NCHUNK * KTOP];
    __shared__ float rd[128];
    __shared__ int   ri[128];
    __shared__ int   rs[128];

    for (int t = tid; t < total; t += 128) {
        size_t off = (size_t)q * total + t;
        cd[t] = g_pd[off];
        ci[t] = g_pi[off];
    }
    __syncthreads();

    for (int it = 0; it < KTOP; it++) {
        float bd = __int_as_float(0x7f800000);
        int   bi = 0x7fffffff, bs = -1;
        for (int t = tid; t < total; t += 128) {
            float d = cd[t]; int i = ci[t];
            if (d < bd || (d == bd && i < bi)) { bd = d; bi = i; bs = t; }
        }
        rd[tid] = bd; ri[tid] = bi; rs[tid] = bs;
        __syncthreads();
        for (int st = 64; st; st >>= 1) {
            if (tid < st) {
                if (rd[tid + st] < rd[tid] ||
                    (rd[tid + st] == rd[tid] && ri[tid + st] < ri[tid])) {
                    rd[tid] = rd[tid + st]; ri[tid] = ri[tid + st]; rs[tid] = rs[tid + st];
                }
            }
            __syncthreads();
        }
        if (tid == 0) {
            out[q * KTOP + it]               = rd[0];                 // distances
            out[QTOT * KTOP + q * KTOP + it] = (float)ri[0];          // indices
            cd[rs[0]] = __int_as_float(0x7f800000);                   // remove winner
        }
        __syncthreads();
    }
}

// ---------------- launcher ----------------
extern "C" void kernel_launch(void* const* d_in, const int* in_sizes, int n_in,
                              void* d_out, int out_size) {
    const float* query = (const float*)d_in[0];
    const float* lib   = (const float*)d_in[1];
    float* out = (float*)d_out;
    (void)n_in; (void)out_size; (void)in_sizes;

    // squared norms: one warp per row
    sqnorm_kernel<<<(NTOT + 7) / 8, 256>>>(lib,   NTOT, 0);
    sqnorm_kernel<<<(QTOT + 7) / 8, 256>>>(query, QTOT, 1);

    // fused distance + per-chunk top-k
    dim3 gridB(NCHUNK, QTOT / QT);
    dist_topk_kernel<<<gridB, 256>>>(query, lib);

    // merge
    merge_kernel<<<QTOT, 128>>>(out);
}

// round 5
// speedup vs baseline: 3.3479x; 3.3479x over previous
#include <cuda_runtime.h>
#include <cuda_bf16.h>
#include <cstdint>

// ---------------- problem constants ----------------
#define D      768
#define QTOT   512
#define NTOT   262144
#define KTOP   10

#define TM     256                 // queries per CTA
#define TN     128                 // lib rows per CTA
#define BK     64                  // k per stage (bf16 elems)
#define NST    (D / BK)            // 12 stages
#define NTILES (NTOT / TN)         // 2048
#define KSEL   24                  // candidates rescored per query

// ---------------- scratch ----------------
__device__ uint4  g_qbf[(size_t)QTOT * D / 8];            // queries as bf16
__device__ float4 g_cd4[(size_t)QTOT * NTILES];           // per-tile top-4 dist
__device__ int4   g_ci4[(size_t)QTOT * NTILES];           // per-tile top-4 idx

// ---------------- helpers ----------------
__device__ __forceinline__ uint32_t smem_u32(const void* p) {
    uint32_t a;
    asm("{ .reg .u64 t; cvta.to.shared.u64 t, %1; cvt.u32.u64 %0, t; }" : "=r"(a) : "l"(p));
    return a;
}
__device__ __forceinline__ unsigned pk_bf2(float a, float b) {
    __nv_bfloat162 t = __floats2bfloat162_rn(a, b);
    return *reinterpret_cast<unsigned*>(&t);
}
#define SWZ(x) ((x) ^ (((x) >> 3) & 0x70))

#define CPASYNC16(dst, src) \
    asm volatile("cp.async.cg.shared.global [%0], [%1], 16;" :: "r"(dst), "l"(src))
#define CPCOMMIT() asm volatile("cp.async.commit_group;" ::: "memory")
#define CPWAIT(n)  asm volatile("cp.async.wait_group %0;" :: "n"(n) : "memory")

__device__ __forceinline__ void ldm_x4(uint32_t* r, uint32_t addr) {
    asm volatile("ldmatrix.sync.aligned.m8n8.x4.shared.b16 {%0,%1,%2,%3}, [%4];"
                 : "=r"(r[0]), "=r"(r[1]), "=r"(r[2]), "=r"(r[3]) : "r"(addr));
}
__device__ __forceinline__ void ldm_x2(uint32_t* r, uint32_t addr) {
    asm volatile("ldmatrix.sync.aligned.m8n8.x2.shared.b16 {%0,%1}, [%2];"
                 : "=r"(r[0]), "=r"(r[1]) : "r"(addr));
}
__device__ __forceinline__ void mma_bf16(float* c, const uint32_t* a, const uint32_t* b) {
    asm volatile("mma.sync.aligned.m16n8k16.row.col.f32.bf16.bf16.f32 "
                 "{%0,%1,%2,%3}, {%4,%5,%6,%7}, {%8,%9}, {%0,%1,%2,%3};"
                 : "+f"(c[0]), "+f"(c[1]), "+f"(c[2]), "+f"(c[3])
                 : "r"(a[0]), "r"(a[1]), "r"(a[2]), "r"(a[3]), "r"(b[0]), "r"(b[1]));
}

// ---------------- kernel 1: query fp32 -> bf16 ----------------
__global__ void qconv_kernel(const float* __restrict__ query) {
    int i = blockIdx.x * 256 + threadIdx.x;          // 49152 granules of 8 bf16
    const float4* src = (const float4*)query;
    float4 a = src[2 * i], b = src[2 * i + 1];
    uint4 o;
    o.x = pk_bf2(a.x, a.y); o.y = pk_bf2(a.z, a.w);
    o.z = pk_bf2(b.x, b.y); o.w = pk_bf2(b.z, b.w);
    g_qbf[i] = o;
}

// ---------------- kernel 2: HMMA GEMM + per-tile approx top-4 ----------------
// dynamic smem layout
#define SA_OFF  0                       // 2 x 32768  (256 rows x 128B)
#define SB_OFF  65536                   // 2 x 16384  (128 rows x 128B)
#define XSQ_OFF 98304                   // 128 floats
#define SMEM_TOTAL (XSQ_OFF + 512)

__global__ __launch_bounds__(512, 1)
void dist_kernel(const float* __restrict__ lib) {
    extern __shared__ char smem[];
    const uint32_t sbase = smem_u32(smem);
    float* xsq_s = (float*)(smem + XSQ_OFF);

    const int tid  = threadIdx.x;
    const int lane = tid & 31;
    const int wid  = tid >> 5;           // 16 warps
    const int wm   = wid >> 2;           // 0..3  (64-row m block)
    const int wn   = wid & 3;            // 0..3  (32-col n block)
    const int bx   = blockIdx.x;
    const int y    = blockIdx.y;         // query half
    const int n0   = bx * TN;
    const int m_base = wm * 64;
    const int n_base = wn * 32;

    if (tid < TN) xsq_s[tid] = 0.f;
    __syncthreads();

    // thread's A-granule assignment: idx = j*512+tid -> row = idx>>3, g = idx&7
    // thread's B-granule assignment: idx = j*512+tid (j<2)

    // prologue: A stage 0 via cp.async, B stage 0 into regs
    {
#pragma unroll
        for (int j = 0; j < 4; j++) {
            int idx = j * 512 + tid;
            int r = idx >> 3, g = idx & 7;
            uint32_t dst = sbase + SA_OFF + SWZ(r * 128 + g * 16);
            const char* src = (const char*)&g_qbf[(size_t)(y * TM + r) * 96 + g];
            CPASYNC16(dst, src);
        }
        CPCOMMIT();
    }
    float4 b_r[4];
#pragma unroll
    for (int j = 0; j < 2; j++) {
        int idx = j * 512 + tid;
        int r = idx >> 3, g = idx & 7;
        const float4* p = (const float4*)(lib + (size_t)(n0 + r) * D + g * 8);
        b_r[j * 2] = p[0]; b_r[j * 2 + 1] = p[1];
    }

    float acc[4][4][4];
#pragma unroll
    for (int a = 0; a < 4; a++)
#pragma unroll
        for (int b = 0; b < 4; b++)
#pragma unroll
            for (int c = 0; c < 4; c++) acc[a][b][c] = 0.f;

    for (int kc = 0; kc < NST; kc++) {
        const int buf = kc & 1;
        // issue A(kc+1) into other buffer (mma(kc-1) that read it is done)
        if (kc + 1 < NST) {
#pragma unroll
            for (int j = 0; j < 4; j++) {
                int idx = j * 512 + tid;
                int r = idx >> 3, g = idx & 7;
                uint32_t dst = sbase + SA_OFF + (buf ^ 1) * 32768 + SWZ(r * 128 + g * 16);
                const char* src = (const char*)&g_qbf[(size_t)(y * TM + r) * 96 + (kc + 1) * 8 + g];
                CPASYNC16(dst, src);
            }
            CPCOMMIT();
        }
        // STS B(kc) (convert + ||x||^2 partial)
        {
            char* Bb = smem + SB_OFF + buf * 16384;
#pragma unroll
            for (int j = 0; j < 2; j++) {
                int idx = j * 512 + tid;
                int r = idx >> 3, g = idx & 7;
                float4 u = b_r[j * 2], v = b_r[j * 2 + 1];
                uint4 o;
                o.x = pk_bf2(u.x, u.y); o.y = pk_bf2(u.z, u.w);
                o.z = pk_bf2(v.x, v.y); o.w = pk_bf2(v.z, v.w);
                *(uint4*)(Bb + SWZ(r * 128 + g * 16)) = o;
                float s = u.x * u.x + u.y * u.y + u.z * u.z + u.w * u.w +
                          v.x * v.x + v.y * v.y + v.z * v.z + v.w * v.w;
                atomicAdd(&xsq_s[r], s);
            }
        }
        if (kc + 1 < NST) { CPWAIT(1); } else { CPWAIT(0); }
        __syncthreads();                     // A(kc) + B(kc) visible everywhere

        if (kc + 1 < NST) {                  // prefetch B(kc+1)
#pragma unroll
            for (int j = 0; j < 2; j++) {
                int idx = j * 512 + tid;
                int r = idx >> 3, g = idx & 7;
                const float4* p = (const float4*)(lib + (size_t)(n0 + r) * D + (kc + 1) * BK + g * 8);
                b_r[j * 2] = p[0]; b_r[j * 2 + 1] = p[1];
            }
        }

        // compute: 4 k16 steps
        const uint32_t aB = sbase + SA_OFF + buf * 32768;
        const uint32_t bB = sbase + SB_OFF + buf * 16384;
#pragma unroll
        for (int s = 0; s < 4; s++) {
            uint32_t afr[4][4], bfr[4][2];
#pragma unroll
            for (int mi = 0; mi < 4; mi++) {
                int row = m_base + mi * 16 + (lane & 15);
                int c16 = 2 * s + (lane >> 4);
                ldm_x4(afr[mi], aB + SWZ(row * 128 + c16 * 16));
            }
#pragma unroll
            for (int ni = 0; ni < 4; ni++) {
                int row = n_base + ni * 8 + (lane & 7);
                int c16 = 2 * s + ((lane >> 3) & 1);
                ldm_x2(bfr[ni], bB + SWZ(row * 128 + c16 * 16));
            }
#pragma unroll
            for (int mi = 0; mi < 4; mi++)
#pragma unroll
                for (int ni = 0; ni < 4; ni++)
                    mma_bf16(acc[mi][ni], afr[mi], bfr[ni]);
        }
        __syncthreads();                     // mma(kc) done before buffers reused
    }

    // ---- epilogue: approx dist + per-(q,tile) top-4 ----
    float* slab  = (float*)(smem + SA_OFF);          // 64 x 128 floats
    float* candd = (float*)(smem + SB_OFF);          // 64 x 32
    int*   candi = (int*)(smem + SB_OFF + 8192);     // 64 x 32

    for (int ms = 0; ms < 4; ms++) {
        __syncthreads();
        if (wm == ms) {
#pragma unroll
            for (int mi = 0; mi < 4; mi++)
#pragma unroll
                for (int ni = 0; ni < 4; ni++)
#pragma unroll
                    for (int c = 0; c < 4; c++) {
                        int row = mi * 16 + (lane >> 2) + (c >> 1) * 8;
                        int col = n_base + ni * 8 + (lane & 3) * 2 + (c & 1);
                        slab[row * 128 + col] = acc[mi][ni][c];
                    }
        }
        __syncthreads();
        // scan: 512 thr = 64 rows x 8 segs x 16 cols
        {
            int r = tid >> 3, seg = tid & 7;
            float t0, t1, t2, t3; int i0, i1, i2, i3;
            t0 = t1 = t2 = t3 = __int_as_float(0x7f800000);
            i0 = i1 = i2 = i3 = 0;
#pragma unroll
            for (int j = 0; j < 16; j++) {
                int col = seg * 16 + j;
                float dh = fmaf(-2.f, slab[r * 128 + col], xsq_s[col]);
                if (dh < t3) {
                    t3 = dh; i3 = n0 + col;
                    if (t3 < t2) { float a = t2; t2 = t3; t3 = a; int bw = i2; i2 = i3; i3 = bw;
                        if (t2 < t1) { a = t1; t1 = t2; t2 = a; bw = i1; i1 = i2; i2 = bw;
                            if (t1 < t0) { a = t0; t0 = t1; t1 = a; bw = i0; i0 = i1; i1 = bw; }
                        }
                    }
                }
            }
            int base = r * 32 + seg * 4;
            candd[base] = t0; candd[base + 1] = t1; candd[base + 2] = t2; candd[base + 3] = t3;
            candi[base] = i0; candi[base + 1] = i1; candi[base + 2] = i2; candi[base + 3] = i3;
        }
        __syncthreads();
        if (tid < 64) {
            float t0, t1, t2, t3; int i0, i1, i2, i3;
            t0 = t1 = t2 = t3 = __int_as_float(0x7f800000);
            i0 = i1 = i2 = i3 = 0x7fffffff;
#pragma unroll
            for (int t = 0; t < 32; t++) {
                float d = candd[tid * 32 + t]; int i = candi[tid * 32 + t];
                if (d < t3 || (d == t3 && i < i3)) {
                    t3 = d; i3 = i;
                    if (t3 < t2 || (t3 == t2 && i3 < i2)) { float a = t2; t2 = t3; t3 = a; int bw = i2; i2 = i3; i3 = bw;
                        if (t2 < t1 || (t2 == t1 && i2 < i1)) { a = t1; t1 = t2; t2 = a; bw = i1; i1 = i2; i2 = bw;
                            if (t1 < t0 || (t1 == t0 && i1 < i0)) { a = t0; t0 = t1; t1 = a; bw = i0; i0 = i1; i1 = bw; }
                        }
                    }
                }
            }
            int q = y * TM + ms * 64 + tid;
            g_cd4[(size_t)q * NTILES + bx] = make_float4(t0, t1, t2, t3);
            g_ci4[(size_t)q * NTILES + bx] = make_int4(i0, i1, i2, i3);
        }
    }
}

// ---------------- kernel 3: merge approx candidates + exact rescore ----------------
__global__ __launch_bounds__(256)
void merge_kernel(const float* __restrict__ query, const float* __restrict__ lib,
                  float* __restrict__ out) {
    __shared__ float qrow[D];
    __shared__ float sd[1536];
    __shared__ int   si[1536];
    __shared__ float wred[8];
    __shared__ int   wredi[8];
    __shared__ int   sel[KSEL];
    __shared__ float ed[KSEL];
    __shared__ int   eidx[KSEL];
    __shared__ float s_qsq;

    const int q = blockIdx.x, tid = threadIdx.x, lane = tid & 31, w = tid >> 5;
    const float INF = __int_as_float(0x7f800000);

    for (int i = tid; i < D; i += 256) qrow[i] = query[(size_t)q * D + i];
    __syncthreads();
    {
        float s = 0.f;
        for (int i = tid; i < D; i += 256) s = fmaf(qrow[i], qrow[i], s);
#pragma unroll
        for (int o = 16; o; o >>= 1) s += __shfl_xor_sync(0xffffffffu, s, o);
        if (lane == 0) wred[w] = s;
        __syncthreads();
        if (tid == 0) { float t = 0.f; for (int i = 0; i < 8; i++) t += wred[i]; s_qsq = t; }
    }

    // local top-6 over strided candidates (2048 tiles x 4 = 8192)
    const float* cd = (const float*)g_cd4 + (size_t)q * NTILES * 4;
    const int*   ci = (const int*)g_ci4 + (size_t)q * NTILES * 4;
    float d6[6]; int x6[6];
#pragma unroll
    for (int j = 0; j < 6; j++) { d6[j] = INF; x6[j] = 0x7fffffff; }
    for (int j = 0; j < 32; j++) {
        int s2 = tid + j * 256;
        float dv = cd[s2]; int iv = ci[s2];
        if (dv < d6[5]) {
            d6[5] = dv; x6[5] = iv;
#pragma unroll
            for (int p = 5; p > 0; p--)
                if (d6[p] < d6[p - 1]) {
                    float a = d6[p]; d6[p] = d6[p - 1]; d6[p - 1] = a;
                    int bw = x6[p]; x6[p] = x6[p - 1]; x6[p - 1] = bw;
                }
        }
    }
#pragma unroll
    for (int j = 0; j < 6; j++) { sd[tid * 6 + j] = d6[j]; si[tid * 6 + j] = x6[j]; }
    __syncthreads();

    // select approx top-24 of 1536
    for (int it = 0; it < KSEL; it++) {
        float bd = INF; int bs = -1;
#pragma unroll
        for (int j = 0; j < 6; j++) {
            int s2 = tid * 6 + j;
            float v = sd[s2];
            if (v < bd) { bd = v; bs = s2; }
        }
#pragma unroll
        for (int o = 16; o; o >>= 1) {
            float od = __shfl_down_sync(0xffffffffu, bd, o);
            int   os = __shfl_down_sync(0xffffffffu, bs, o);
            if (od < bd) { bd = od; bs = os; }
        }
        if (lane == 0) { wred[w] = bd; wredi[w] = bs; }
        __syncthreads();
        if (tid == 0) {
            float m = INF; int ms = -1;
            for (int ww = 0; ww < 8; ww++) if (wred[ww] < m) { m = wred[ww]; ms = wredi[ww]; }
            sel[it] = si[ms];
            sd[ms] = INF;
        }
        __syncthreads();
    }

    // exact fp32 rescore of the 24 candidates
    for (int c = w; c < KSEL; c += 8) {
        int n = sel[c];
        const float* xr = lib + (size_t)n * D;
        float dot = 0.f, ssq = 0.f;
#pragma unroll
        for (int j = 0; j < D / 32; j++) {
            float xv = xr[lane + j * 32], qv = qrow[lane + j * 32];
            dot = fmaf(qv, xv, dot);
            ssq = fmaf(xv, xv, ssq);
        }
#pragma unroll
        for (int o = 16; o; o >>= 1) {
            dot += __shfl_xor_sync(0xffffffffu, dot, o);
            ssq += __shfl_xor_sync(0xffffffffu, ssq, o);
        }
        if (lane == 0) { ed[c] = s_qsq - 2.f * dot + ssq; eidx[c] = n; }
    }
    __syncthreads();

    // exact top-10 with index tie-break
    if (tid == 0) {
        unsigned used = 0;
        for (int it = 0; it < KTOP; it++) {
            float bd = INF; int bi = 0x7fffffff, b = -1;
            for (int c = 0; c < KSEL; c++)
                if (!((used >> c) & 1u)) {
                    if (ed[c] < bd || (ed[c] == bd && eidx[c] < bi)) { bd = ed[c]; bi = eidx[c]; b = c; }
                }
            used |= 1u << b;
            out[q * KTOP + it]               = bd;
            out[QTOT * KTOP + q * KTOP + it] = (float)bi;
        }
    }
}

// ---------------- launcher ----------------
extern "C" void kernel_launch(void* const* d_in, const int* in_sizes, int n_in,
                              void* d_out, int out_size) {
    const float* query = (const float*)d_in[0];
    const float* lib   = (const float*)d_in[1];
    float* out = (float*)d_out;
    (void)n_in; (void)out_size; (void)in_sizes;

    cudaFuncSetAttribute(dist_kernel,
                         cudaFuncAttributeMaxDynamicSharedMemorySize, SMEM_TOTAL);

    qconv_kernel<<<QTOT * D / 8 / 256, 256>>>(query);
    dim3 grid(NTOT / TN, QTOT / TM);
    dist_kernel<<<grid, 512, SMEM_TOTAL>>>(lib);
    merge_kernel<<<QTOT, 256>>>(query, lib, out);
}

// round 6
// speedup vs baseline: 4.3129x; 1.2882x over previous
#include <cuda_runtime.h>
#include <cuda_bf16.h>
#include <cstdint>

// ---------------- problem constants ----------------
#define D      768
#define QTOT   512
#define NTOT   262144
#define KTOP   10

#define TM     256                 // queries per CTA
#define TN     128                 // lib rows per CTA
#define BK     64                  // k per stage (bf16 elems)
#define NST    (D / BK)            // 12 stages
#define NTILES (NTOT / TN)         // 2048
#define KSEL   24                  // candidates rescored per query

// ---------------- scratch ----------------
__device__ uint4  g_qbf[(size_t)QTOT * D / 8];            // queries as bf16
__device__ float4 g_cd4[(size_t)QTOT * NTILES];           // per-tile top-4 dist
__device__ int4   g_ci4[(size_t)QTOT * NTILES];           // per-tile top-4 idx

// ---------------- helpers ----------------
__device__ __forceinline__ uint32_t smem_u32(const void* p) {
    uint32_t a;
    asm("{ .reg .u64 t; cvta.to.shared.u64 t, %1; cvt.u32.u64 %0, t; }" : "=r"(a) : "l"(p));
    return a;
}
__device__ __forceinline__ unsigned pk_bf2(float a, float b) {
    __nv_bfloat162 t = __floats2bfloat162_rn(a, b);
    return *reinterpret_cast<unsigned*>(&t);
}
#define SWZ(x) ((x) ^ (((x) >> 3) & 0x70))

#define CPASYNC16(dst, src) \
    asm volatile("cp.async.cg.shared.global [%0], [%1], 16;" :: "r"(dst), "l"(src))
#define CPCOMMIT() asm volatile("cp.async.commit_group;" ::: "memory")
#define CPWAIT(n)  asm volatile("cp.async.wait_group %0;" :: "n"(n) : "memory")

__device__ __forceinline__ void ldm_x4(uint32_t* r, uint32_t addr) {
    asm volatile("ldmatrix.sync.aligned.m8n8.x4.shared.b16 {%0,%1,%2,%3}, [%4];"
                 : "=r"(r[0]), "=r"(r[1]), "=r"(r[2]), "=r"(r[3]) : "r"(addr));
}
__device__ __forceinline__ void mma_bf16(float* c, const uint32_t* a, const uint32_t* b) {
    asm volatile("mma.sync.aligned.m16n8k16.row.col.f32.bf16.bf16.f32 "
                 "{%0,%1,%2,%3}, {%4,%5,%6,%7}, {%8,%9}, {%0,%1,%2,%3};"
                 : "+f"(c[0]), "+f"(c[1]), "+f"(c[2]), "+f"(c[3])
                 : "r"(a[0]), "r"(a[1]), "r"(a[2]), "r"(a[3]), "r"(b[0]), "r"(b[1]));
}

// ---------------- kernel 1: query fp32 -> bf16 ----------------
__global__ void qconv_kernel(const float* __restrict__ query) {
    int i = blockIdx.x * 256 + threadIdx.x;
    const float4* src = (const float4*)query;
    float4 a = src[2 * i], b = src[2 * i + 1];
    uint4 o;
    o.x = pk_bf2(a.x, a.y); o.y = pk_bf2(a.z, a.w);
    o.z = pk_bf2(b.x, b.y); o.w = pk_bf2(b.z, b.w);
    g_qbf[i] = o;
}

// ---------------- kernel 2: HMMA GEMM + per-tile approx top-4 ----------------
#define SA_OFF  0                       // 2 x 32768  (256 rows x 128B)
#define SB_OFF  65536                   // 2 x 16384  (128 rows x 128B)
#define XSQ_OFF 98304                   // 128 floats
#define SMEM_TOTAL (XSQ_OFF + 512)

__global__ __launch_bounds__(256, 1)
void dist_kernel(const float* __restrict__ lib) {
    extern __shared__ char smem[];
    const uint32_t sbase = smem_u32(smem);
    float* xsq_s = (float*)(smem + XSQ_OFF);

    const int tid  = threadIdx.x;
    const int lane = tid & 31;
    const int wid  = tid >> 5;           // 8 warps
    const int wm   = wid >> 1;           // 0..3 (64-row m block)
    const int wn   = wid & 1;            // 0..1 (64-col n block)
    const int bx   = blockIdx.x;
    const int y    = blockIdx.y;
    const int n0   = bx * TN;
    const int m_base = wm * 64;
    const int n_base = wn * 64;

    if (tid < TN) xsq_s[tid] = 0.f;
    __syncthreads();

    // prologue: A(0) via cp.async, B(0) fp32 into regs
#pragma unroll
    for (int j = 0; j < 8; j++) {
        int idx = j * 256 + tid;
        int r = idx >> 3, g = idx & 7;
        uint32_t dst = sbase + SA_OFF + SWZ(r * 128 + g * 16);
        CPASYNC16(dst, (const char*)&g_qbf[(size_t)(y * TM + r) * 96 + g]);
    }
    CPCOMMIT();

    float4 b_r[8];
    {
        const int g = tid & 15, rb = tid >> 4;
#pragma unroll
        for (int j = 0; j < 8; j++) {
            int r = j * 16 + rb;
            b_r[j] = *(const float4*)(lib + (size_t)(n0 + r) * D + g * 4);
        }
    }

    float acc[4][8][4];
#pragma unroll
    for (int a = 0; a < 4; a++)
#pragma unroll
        for (int b = 0; b < 8; b++)
#pragma unroll
            for (int c = 0; c < 4; c++) acc[a][b][c] = 0.f;

    for (int kc = 0; kc < NST; kc++) {
        const int buf = kc & 1;
        // A(kc+1) into other buffer
        if (kc + 1 < NST) {
#pragma unroll
            for (int j = 0; j < 8; j++) {
                int idx = j * 256 + tid;
                int r = idx >> 3, g = idx & 7;
                uint32_t dst = sbase + SA_OFF + (buf ^ 1) * 32768 + SWZ(r * 128 + g * 16);
                CPASYNC16(dst, (const char*)&g_qbf[(size_t)(y * TM + r) * 96 + (kc + 1) * 8 + g]);
            }
            CPCOMMIT();
        }
        // convert B(kc) regs -> bf16 smem, fused ||x||^2
        {
            char* Bb = smem + SB_OFF + buf * 16384;
            const int g = tid & 15, rb = tid >> 4;
#pragma unroll
            for (int j = 0; j < 8; j++) {
                int r = j * 16 + rb;
                float4 v = b_r[j];
                uint2 o;
                o.x = pk_bf2(v.x, v.y); o.y = pk_bf2(v.z, v.w);
                uint32_t off = SWZ(r * 128 + (g >> 1) * 16) + (g & 1) * 8;
                *(uint2*)(Bb + off) = o;
                float s = v.x * v.x + v.y * v.y + v.z * v.z + v.w * v.w;
#pragma unroll
                for (int o2 = 1; o2 < 16; o2 <<= 1) s += __shfl_xor_sync(0xffffffffu, s, o2);
                if ((lane & 15) == 0) atomicAdd(&xsq_s[r], s);
            }
        }
        if (kc + 1 < NST) { CPWAIT(1); } else { CPWAIT(0); }
        __syncthreads();                     // A(kc) + B(kc) visible

        if (kc + 1 < NST) {                  // prefetch B(kc+1) fp32
            const int g = tid & 15, rb = tid >> 4;
#pragma unroll
            for (int j = 0; j < 8; j++) {
                int r = j * 16 + rb;
                b_r[j] = *(const float4*)(lib + (size_t)(n0 + r) * D + (kc + 1) * BK + g * 4);
            }
        }

        // compute: 4 k16 steps
        const uint32_t aB = sbase + SA_OFF + buf * 32768;
        const uint32_t bB = sbase + SB_OFF + buf * 16384;
#pragma unroll
        for (int s = 0; s < 4; s++) {
            uint32_t afr[4][4], bfr[8][2];
#pragma unroll
            for (int mi = 0; mi < 4; mi++) {
                int row = m_base + mi * 16 + (lane & 15);
                int c16 = 2 * s + (lane >> 4);
                ldm_x4(afr[mi], aB + SWZ(row * 128 + c16 * 16));
            }
#pragma unroll
            for (int nb = 0; nb < 4; nb++) {
                uint32_t t4[4];
                int row = n_base + nb * 16 + (lane & 7) + ((lane >> 4) << 3);
                int c16 = 2 * s + ((lane >> 3) & 1);
                ldm_x4(t4, bB + SWZ(row * 128 + c16 * 16));
                bfr[nb * 2][0] = t4[0]; bfr[nb * 2][1] = t4[1];
                bfr[nb * 2 + 1][0] = t4[2]; bfr[nb * 2 + 1][1] = t4[3];
            }
#pragma unroll
            for (int mi = 0; mi < 4; mi++)
#pragma unroll
                for (int ni = 0; ni < 8; ni++)
                    mma_bf16(acc[mi][ni], afr[mi], bfr[ni]);
        }
        __syncthreads();                     // buffers reusable
    }

    // ---- epilogue: approx dist + per-(q,tile) top-4 ----
    float* slab  = (float*)(smem + SA_OFF);          // 64 x 128 floats
    float* candd = (float*)(smem + SB_OFF);          // 64 x 16
    int*   candi = (int*)(smem + SB_OFF + 4096);     // 64 x 16

    for (int ms = 0; ms < 4; ms++) {
        __syncthreads();
        if (wm == ms) {
#pragma unroll
            for (int mi = 0; mi < 4; mi++)
#pragma unroll
                for (int ni = 0; ni < 8; ni++)
#pragma unroll
                    for (int c = 0; c < 4; c++) {
                        int row = mi * 16 + (lane >> 2) + (c >> 1) * 8;
                        int col = n_base + ni * 8 + (lane & 3) * 2 + (c & 1);
                        slab[row * 128 + col] = acc[mi][ni][c];
                    }
        }
        __syncthreads();
        // scan: 256 thr = 64 rows x 4 segs x 32 cols
        {
            int r = tid >> 2, seg = tid & 3;
            float t0, t1, t2, t3; int i0, i1, i2, i3;
            t0 = t1 = t2 = t3 = __int_as_float(0x7f800000);
            i0 = i1 = i2 = i3 = 0;
#pragma unroll
            for (int j = 0; j < 32; j++) {
                int col = seg * 32 + j;
                float dh = fmaf(-2.f, slab[r * 128 + col], xsq_s[col]);
                if (dh < t3) {
                    t3 = dh; i3 = n0 + col;
                    if (t3 < t2) { float a = t2; t2 = t3; t3 = a; int bw = i2; i2 = i3; i3 = bw;
                        if (t2 < t1) { a = t1; t1 = t2; t2 = a; bw = i1; i1 = i2; i2 = bw;
                            if (t1 < t0) { a = t0; t0 = t1; t1 = a; bw = i0; i0 = i1; i1 = bw; }
                        }
                    }
                }
            }
            int base = r * 16 + seg * 4;
            candd[base] = t0; candd[base + 1] = t1; candd[base + 2] = t2; candd[base + 3] = t3;
            candi[base] = i0; candi[base + 1] = i1; candi[base + 2] = i2; candi[base + 3] = i3;
        }
        __syncthreads();
        if (tid < 64) {
            float t0, t1, t2, t3; int i0, i1, i2, i3;
            t0 = t1 = t2 = t3 = __int_as_float(0x7f800000);
            i0 = i1 = i2 = i3 = 0x7fffffff;
#pragma unroll
            for (int t = 0; t < 16; t++) {
                float d = candd[tid * 16 + t]; int i = candi[tid * 16 + t];
                if (d < t3 || (d == t3 && i < i3)) {
                    t3 = d; i3 = i;
                    if (t3 < t2 || (t3 == t2 && i3 < i2)) { float a = t2; t2 = t3; t3 = a; int bw = i2; i2 = i3; i3 = bw;
                        if (t2 < t1 || (t2 == t1 && i2 < i1)) { a = t1; t1 = t2; t2 = a; bw = i1; i1 = i2; i2 = bw;
                            if (t1 < t0 || (t1 == t0 && i1 < i0)) { a = t0; t0 = t1; t1 = a; bw = i0; i0 = i1; i1 = bw; }
                        }
                    }
                }
            }
            int q = y * TM + ms * 64 + tid;
            g_cd4[(size_t)q * NTILES + bx] = make_float4(t0, t1, t2, t3);
            g_ci4[(size_t)q * NTILES + bx] = make_int4(i0, i1, i2, i3);
        }
    }
}

// ---------------- kernel 3: merge approx candidates + exact rescore ----------------
__global__ __launch_bounds__(256)
void merge_kernel(const float* __restrict__ query, const float* __restrict__ lib,
                  float* __restrict__ out) {
    __shared__ float qrow[D];
    __shared__ float sd[1536];
    __shared__ int   si[1536];
    __shared__ float wred[8];
    __shared__ int   wredi[8];
    __shared__ int   sel[KSEL];
    __shared__ float ed[KSEL];
    __shared__ int   eidx[KSEL];
    __shared__ float s_qsq;

    const int q = blockIdx.x, tid = threadIdx.x, lane = tid & 31, w = tid >> 5;
    const float INF = __int_as_float(0x7f800000);

    for (int i = tid; i < D; i += 256) qrow[i] = query[(size_t)q * D + i];
    __syncthreads();
    {
        float s = 0.f;
        for (int i = tid; i < D; i += 256) s = fmaf(qrow[i], qrow[i], s);
#pragma unroll
        for (int o = 16; o; o >>= 1) s += __shfl_xor_sync(0xffffffffu, s, o);
        if (lane == 0) wred[w] = s;
        __syncthreads();
        if (tid == 0) { float t = 0.f; for (int i = 0; i < 8; i++) t += wred[i]; s_qsq = t; }
    }

    const float* cd = (const float*)g_cd4 + (size_t)q * NTILES * 4;
    const int*   ci = (const int*)g_ci4 + (size_t)q * NTILES * 4;
    float d6[6]; int x6[6];
#pragma unroll
    for (int j = 0; j < 6; j++) { d6[j] = INF; x6[j] = 0x7fffffff; }
    for (int j = 0; j < 32; j++) {
        int s2 = tid + j * 256;
        float dv = cd[s2]; int iv = ci[s2];
        if (dv < d6[5]) {
            d6[5] = dv; x6[5] = iv;
#pragma unroll
            for (int p = 5; p > 0; p--)
                if (d6[p] < d6[p - 1]) {
                    float a = d6[p]; d6[p] = d6[p - 1]; d6[p - 1] = a;
                    int bw = x6[p]; x6[p] = x6[p - 1]; x6[p - 1] = bw;
                }
        }
    }
#pragma unroll
    for (int j = 0; j < 6; j++) { sd[tid * 6 + j] = d6[j]; si[tid * 6 + j] = x6[j]; }
    __syncthreads();

    for (int it = 0; it < KSEL; it++) {
        float bd = INF; int bs = -1;
#pragma unroll
        for (int j = 0; j < 6; j++) {
            int s2 = tid * 6 + j;
            float v = sd[s2];
            if (v < bd) { bd = v; bs = s2; }
        }
#pragma unroll
        for (int o = 16; o; o >>= 1) {
            float od = __shfl_down_sync(0xffffffffu, bd, o);
            int   os = __shfl_down_sync(0xffffffffu, bs, o);
            if (od < bd) { bd = od; bs = os; }
        }
        if (lane == 0) { wred[w] = bd; wredi[w] = bs; }
        __syncthreads();
        if (tid == 0) {
            float m = INF; int ms = -1;
            for (int ww = 0; ww < 8; ww++) if (wred[ww] < m) { m = wred[ww]; ms = wredi[ww]; }
            sel[it] = si[ms];
            sd[ms] = INF;
        }
        __syncthreads();
    }

    for (int c = w; c < KSEL; c += 8) {
        int n = sel[c];
        const float* xr = lib + (size_t)n * D;
        float dot = 0.f, ssq = 0.f;
#pragma unroll
        for (int j = 0; j < D / 32; j++) {
            float xv = xr[lane + j * 32], qv = qrow[lane + j * 32];
            dot = fmaf(qv, xv, dot);
            ssq = fmaf(xv, xv, ssq);
        }
#pragma unroll
        for (int o = 16; o; o >>= 1) {
            dot += __shfl_xor_sync(0xffffffffu, dot, o);
            ssq += __shfl_xor_sync(0xffffffffu, ssq, o);
        }
        if (lane == 0) { ed[c] = s_qsq - 2.f * dot + ssq; eidx[c] = n; }
    }
    __syncthreads();

    if (tid == 0) {
        unsigned used = 0;
        for (int it = 0; it < KTOP; it++) {
            float bd = INF; int bi = 0x7fffffff, b = -1;
            for (int c = 0; c < KSEL; c++)
                if (!((used >> c) & 1u)) {
                    if (ed[c] < bd || (ed[c] == bd && eidx[c] < bi)) { bd = ed[c]; bi = eidx[c]; b = c; }
                }
            used |= 1u << b;
            out[q * KTOP + it]               = bd;
            out[QTOT * KTOP + q * KTOP + it] = (float)bi;
        }
    }
}

// ---------------- launcher ----------------
extern "C" void kernel_launch(void* const* d_in, const int* in_sizes, int n_in,
                              void* d_out, int out_size) {
    const float* query = (const float*)d_in[0];
    const float* lib   = (const float*)d_in[1];
    float* out = (float*)d_out;
    (void)n_in; (void)out_size; (void)in_sizes;

    cudaFuncSetAttribute(dist_kernel,
                         cudaFuncAttributeMaxDynamicSharedMemorySize, SMEM_TOTAL);

    qconv_kernel<<<QTOT * D / 8 / 256, 256>>>(query);
    dim3 grid(NTOT / TN, QTOT / TM);
    dist_kernel<<<grid, 256, SMEM_TOTAL>>>(lib);
    merge_kernel<<<QTOT, 256>>>(query, lib, out);
}